// round 12
// baseline (speedup 1.0000x reference)
#include <cuda_runtime.h>
#include <cuda_fp16.h>
#include <cstdint>

// Problem constants
constexpr int D  = 1024;   // d_model
constexpr int S  = 2048;   // sequence length
constexpr int B  = 2;      // batch
constexpr int H  = 16;     // heads
constexpr int DH = 64;     // head dim
constexpr int M  = B * S;  // 4096 rows

// Scratch (device globals; no allocations allowed). 16B-aligned for cp.async.
__device__ __align__(256) __half g_x[M * D];
__device__ __align__(256) __half g_y[M * D];
__device__ __align__(256) __half g_wq[D * D];
__device__ __align__(256) __half g_wk[D * D];
__device__ __align__(256) __half g_wv[D * D];
__device__ __align__(256) __half g_wo[D * D];
__device__ __align__(256) __half g_q[M * D];     // head-split [B,H,S,DH]
__device__ __align__(256) __half g_k[M * D];
__device__ __align__(256) __half g_v[M * D];
__device__ __align__(256) __half g_att[M * D];   // [B,S,H*DH]
__device__ int g_mask_nz;                         // 1 if mask has any nonzero

// ---------------------------------------------------------------------------
// helpers
// ---------------------------------------------------------------------------
__device__ __forceinline__ void cp16(const void* smem_dst, const void* gmem_src) {
    unsigned d = (unsigned)__cvta_generic_to_shared(smem_dst);
    asm volatile("cp.async.cg.shared.global [%0], [%1], 16;" :: "r"(d), "l"(gmem_src));
}
__device__ __forceinline__ void cp_commit() { asm volatile("cp.async.commit_group;"); }
__device__ __forceinline__ void cp_wait0()  { asm volatile("cp.async.wait_group 0;"); }
__device__ __forceinline__ void cp_wait1()  { asm volatile("cp.async.wait_group 1;"); }
__device__ __forceinline__ void cp_wait2()  { asm volatile("cp.async.wait_group 2;"); }

__device__ __forceinline__ uint32_t smem_u32(const void* p) {
    return (uint32_t)__cvta_generic_to_shared(p);
}

// D = A*B + D   (m16n8k16, f16 inputs, f32 accum)
__device__ __forceinline__ void mma16(float c[4],
                                      unsigned a0, unsigned a1, unsigned a2, unsigned a3,
                                      unsigned b0, unsigned b1) {
    asm volatile(
        "mma.sync.aligned.m16n8k16.row.col.f32.f16.f16.f32 "
        "{%0,%1,%2,%3},{%4,%5,%6,%7},{%8,%9},{%0,%1,%2,%3};"
        : "+f"(c[0]), "+f"(c[1]), "+f"(c[2]), "+f"(c[3])
        : "r"(a0), "r"(a1), "r"(a2), "r"(a3), "r"(b0), "r"(b1));
}

__device__ __forceinline__ void ldm_x4(unsigned r[4], uint32_t addr) {
    asm volatile("ldmatrix.sync.aligned.m8n8.x4.shared.b16 {%0,%1,%2,%3}, [%4];"
                 : "=r"(r[0]), "=r"(r[1]), "=r"(r[2]), "=r"(r[3]) : "r"(addr));
}

// ---------------------------------------------------------------------------
// Merged elementwise fp16 conversion + mask nonzero check (z = 6).
// ---------------------------------------------------------------------------
__global__ void cvt_all(const float4* __restrict__ x,  const float4* __restrict__ y,
                        const float4* __restrict__ wq, const float4* __restrict__ wk,
                        const float4* __restrict__ wv, const float4* __restrict__ wo,
                        const float4* __restrict__ mask)
{
    if (blockIdx.z == 6) {     // mask check (flag pre-cleared by memset)
        int found = 0;
        const int n4 = S * S / 4;
        for (int i = blockIdx.x * blockDim.x + threadIdx.x; i < n4;
             i += gridDim.x * blockDim.x) {
            float4 v = mask[i];
            if (v.x != 0.f || v.y != 0.f || v.z != 0.f || v.w != 0.f) { found = 1; break; }
        }
        if (__syncthreads_or(found)) {
            if (threadIdx.x == 0) atomicOr(&g_mask_nz, 1);
        }
        return;
    }
    const float4* src; uint2* dst; int n4;
    switch (blockIdx.z) {
        case 0: src = x;  dst = (uint2*)g_x;  n4 = M * D / 4; break;
        case 1: src = y;  dst = (uint2*)g_y;  n4 = M * D / 4; break;
        case 2: src = wq; dst = (uint2*)g_wq; n4 = D * D / 4; break;
        case 3: src = wk; dst = (uint2*)g_wk; n4 = D * D / 4; break;
        case 4: src = wv; dst = (uint2*)g_wv; n4 = D * D / 4; break;
        default: src = wo; dst = (uint2*)g_wo; n4 = D * D / 4; break;
    }
    for (int i = blockIdx.x * blockDim.x + threadIdx.x; i < n4;
         i += gridDim.x * blockDim.x) {
        float4 v = src[i];
        __half2 h01 = __floats2half2_rn(v.x, v.y);
        __half2 h23 = __floats2half2_rn(v.z, v.w);
        uint2 u;
        u.x = *reinterpret_cast<unsigned*>(&h01);
        u.y = *reinterpret_cast<unsigned*>(&h23);
        dst[i] = u;
    }
}

// ---------------------------------------------------------------------------
// GEMM: C = A[.,1024] @ W[1024,1024]^T, fp16 mma.
// CTA tile 128x256, BK=64 halfs, 256 thr, 8 warps (2m x 4n), warp tile 64x64.
// 3-stage cp.async ring. All fragments via ldmatrix.x4.
// mode 0: f32 row-major out; mode 1: head-split f16 out.
// ---------------------------------------------------------------------------
constexpr int GSTRIDE = 72;                     // halfs per smem row (64 + 8 pad)
constexpr int AROWS = 128, BROWS = 256;
constexpr int ATILE = AROWS * GSTRIDE;          // halfs
constexpr int STG   = (AROWS + BROWS) * GSTRIDE; // halfs per stage (27648)
constexpr int GEMM_SMEM = 3 * STG * 2;          // 165888 B

__device__ __forceinline__
void gemm_body(const __half* __restrict__ A, const __half* __restrict__ W,
               void* __restrict__ Cout, int mode, int bx, int by)
{
    extern __shared__ __half smh[];
    const int tid    = threadIdx.x;
    const int lane   = tid & 31;
    const int warp   = tid >> 5;
    const int warp_m = warp >> 2;    // 0..1
    const int warp_n = warp & 3;     // 0..3
    const int m0 = by * 128;
    const int n0 = bx * 256;
    const int lr = lane >> 2;        // 0..7
    const int lc = lane & 3;         // 0..3
    const int t8 = lane >> 3;        // ldmatrix tile id 0..3
    const int rI = lane & 7;         // row within tile

    // ldmatrix source offsets (in halfs)
    const int aOff = (warp_m * 64 + (t8 & 1) * 8 + rI) * GSTRIDE + (t8 >> 1) * 8;
    const int wOff = (warp_n * 64 + (t8 >> 1) * 8 + rI) * GSTRIDE + (t8 & 1) * 8;

    float acc[4][8][4];
#pragma unroll
    for (int i = 0; i < 4; i++)
#pragma unroll
        for (int j = 0; j < 8; j++)
#pragma unroll
            for (int t = 0; t < 4; t++) acc[i][j][t] = 0.f;

    auto load_stage = [&](int kc, __half* Sg) {
        const __half* Ap = A + (size_t)m0 * D + kc * 64;
        const __half* Wp = W + (size_t)n0 * D + kc * 64;
        __half* As = Sg;
        __half* Ws = Sg + ATILE;
#pragma unroll
        for (int t = 0; t < 4; t++) {          // A: 128 rows x 8 seg = 1024
            int idx = tid + 256 * t;
            int row = idx >> 3;
            int seg = idx & 7;
            cp16(As + row * GSTRIDE + seg * 8, Ap + (size_t)row * D + seg * 8);
        }
#pragma unroll
        for (int t = 0; t < 8; t++) {          // B: 256 rows x 8 seg = 2048
            int idx = tid + 256 * t;
            int row = idx >> 3;
            int seg = idx & 7;
            cp16(Ws + row * GSTRIDE + seg * 8, Wp + (size_t)row * D + seg * 8);
        }
    };

    load_stage(0, smh);
    cp_commit();
    load_stage(1, smh + STG);
    cp_commit();

    for (int kt = 0; kt < 16; kt++) {
        __syncthreads();            // all reads of recycled buffer done
        if (kt + 2 < 16) {
            load_stage(kt + 2, smh + ((kt + 2) % 3) * STG);
            cp_commit();
        }
        if (kt <= 13) cp_wait2();
        else if (kt == 14) cp_wait1();
        else cp_wait0();
        __syncthreads();            // stage kt visible to all

        const __half* As = smh + (kt % 3) * STG;
        const __half* Ws = As + ATILE;

#pragma unroll
        for (int ks = 0; ks < 4; ks++) {
            unsigned a[4][4];
#pragma unroll
            for (int mt = 0; mt < 4; mt++)
                ldm_x4(a[mt], smem_u32(As + aOff + mt * (16 * GSTRIDE) + ks * 16));
#pragma unroll
            for (int nt2 = 0; nt2 < 4; nt2++) {
                unsigned b[4];
                ldm_x4(b, smem_u32(Ws + wOff + nt2 * (16 * GSTRIDE) + ks * 16));
#pragma unroll
                for (int mt = 0; mt < 4; mt++) {
                    mma16(acc[mt][2 * nt2],     a[mt][0], a[mt][1], a[mt][2], a[mt][3], b[0], b[1]);
                    mma16(acc[mt][2 * nt2 + 1], a[mt][0], a[mt][1], a[mt][2], a[mt][3], b[2], b[3]);
                }
            }
        }
    }

#pragma unroll
    for (int mt = 0; mt < 4; mt++) {
#pragma unroll
        for (int nt = 0; nt < 8; nt++) {
            int rA = m0 + warp_m * 64 + mt * 16 + lr;
            int cA = n0 + warp_n * 64 + nt * 8 + 2 * lc;
#pragma unroll
            for (int half_i = 0; half_i < 2; half_i++) {
                int m = rA + half_i * 8;
                float v0 = acc[mt][nt][half_i * 2 + 0];
                float v1 = acc[mt][nt][half_i * 2 + 1];
                if (mode == 0) {
                    *(float2*)((float*)Cout + (size_t)m * D + cA) = make_float2(v0, v1);
                } else {
                    int bb = m >> 11;
                    int ss = m & (S - 1);
                    int hh = cA >> 6;
                    int dh = cA & (DH - 1);
                    __half* dst = (__half*)Cout + (((size_t)(bb * H + hh) * S + ss) * DH + dh);
                    *(__half2*)dst = __floats2half2_rn(v0, v1);
                }
            }
        }
    }
}

__global__ __launch_bounds__(256, 1)
void qkv_gemm()
{
    const __half* A; const __half* W; __half* C;
    if (blockIdx.z == 0)      { A = g_y; W = g_wq; C = g_q; }
    else if (blockIdx.z == 1) { A = g_x; W = g_wk; C = g_k; }
    else                      { A = g_x; W = g_wv; C = g_v; }
    gemm_body(A, W, C, 1, blockIdx.x, blockIdx.y);
}

__global__ __launch_bounds__(256, 1)
void o_gemm(float* __restrict__ Out)
{
    gemm_body(g_att, g_wo, Out, 0, blockIdx.x, blockIdx.y);
}

// ---------------------------------------------------------------------------
// Flash attention (unchanged from round 11), naive softmax, fp16 mma,
// cp.async double-buffered K/V. CTA = 128 q-rows, 256 thr / 8 warps.
// P kept in registers; K via ldmatrix.x4; V via ldmatrix.x4.trans.
// ---------------------------------------------------------------------------
constexpr int KST = 64 * 72;     // halfs per K/V stage
constexpr int ATTN_SMEM = (4 * KST + 128 * 72) * 2;   // 55296 B

__global__ __launch_bounds__(256, 2)
void flash_attn(const float* __restrict__ mask)
{
    extern __shared__ __half smh[];
    __half* Ks2 = smh;               // 2 stages of 64x72
    __half* Vs2 = smh + 2 * KST;     // 2 stages of 64x72
    __half* Qs  = smh + 4 * KST;     // 128 x 72 (Q staging only)

    const int tid  = threadIdx.x;
    const int lane = tid & 31;
    const int warp = tid >> 5;
    const int lr = lane >> 2;      // 0..7
    const int lc = lane & 3;       // 0..3
    const int t8 = lane >> 3;      // ldmatrix tile id
    const int rI = lane & 7;
    const int bh = blockIdx.y;
    const int qb = blockIdx.x * 128;
    const int mnz = g_mask_nz;     // uniform per launch

    const __half* qp    = g_q + ((size_t)bh * S + qb) * DH;
    const __half* kbase = g_k + (size_t)bh * S * DH;
    const __half* vbase = g_v + (size_t)bh * S * DH;

    const int kOff = ((t8 >> 1) * 8 + rI) * 72 + (t8 & 1) * 8;

    auto kv_load = [&](int kb, __half* Kd, __half* Vd) {
#pragma unroll
        for (int t = 0; t < 2; t++) {
            int idx = tid + 256 * t;   // 0..511
            int row = idx >> 3;        // 0..63
            int seg = idx & 7;
            cp16(Kd + row * 72 + seg * 8, kbase + (size_t)(kb + row) * DH + seg * 8);
        }
#pragma unroll
        for (int t = 0; t < 2; t++) {
            int idx = tid + 256 * t;
            int row = idx >> 3;
            int seg = idx & 7;
            cp16(Vd + row * 72 + seg * 8, vbase + (size_t)(kb + row) * DH + seg * 8);
        }
    };

    // Stage Q (128 x 64 halfs)
#pragma unroll
    for (int t = 0; t < 4; t++) {
        int idx = tid + 256 * t;       // 0..1023
        int row = idx >> 3;            // 0..127
        int seg = idx & 7;
        cp16(&Qs[row * 72 + seg * 8], qp + (size_t)row * DH + seg * 8);
    }
    cp_commit();
    kv_load(0, Ks2, Vs2);
    cp_commit();
    cp_wait1();          // Q complete (KV0 may still be in flight)
    __syncthreads();

    const int r0 = warp * 16 + lr;       // warp-local q row (of 128)

    // Q fragments in registers for the whole loop (DH=64 -> 4 k16 steps)
    unsigned qf[4][4];
#pragma unroll
    for (int ks = 0; ks < 4; ks++) {
        const int kc = ks * 16 + 2 * lc;
        qf[ks][0] = *(const unsigned*)&Qs[r0 * 72 + kc];
        qf[ks][1] = *(const unsigned*)&Qs[(r0 + 8) * 72 + kc];
        qf[ks][2] = *(const unsigned*)&Qs[r0 * 72 + kc + 8];
        qf[ks][3] = *(const unsigned*)&Qs[(r0 + 8) * 72 + kc + 8];
    }

    float accO[8][4];
#pragma unroll
    for (int i = 0; i < 8; i++)
#pragma unroll
        for (int t = 0; t < 4; t++) accO[i][t] = 0.f;
    float rs0 = 0.f, rs1 = 0.f;

    for (int kt = 0; kt < S / 64; kt++) {
        const int s = kt & 1;
        if (kt < S / 64 - 1) {
            kv_load((kt + 1) * 64, Ks2 + (s ^ 1) * KST, Vs2 + (s ^ 1) * KST);
            cp_commit();
            cp_wait1();     // KV[kt] done, KV[kt+1] in flight
        } else {
            cp_wait0();
        }
        __syncthreads();    // KV[kt] visible; prior-stage reads done

        const __half* Ks = Ks2 + s * KST;
        const __half* Vs = Vs2 + s * KST;
        const int kb = kt * 64;

        // S = Q K^T  (warp: 16 x 64), K B-frags via ldmatrix.x4
        float sAcc[8][4];
#pragma unroll
        for (int i = 0; i < 8; i++)
#pragma unroll
            for (int t = 0; t < 4; t++) sAcc[i][t] = 0.f;
#pragma unroll
        for (int ks = 0; ks < 4; ks++) {
#pragma unroll
            for (int nt2 = 0; nt2 < 4; nt2++) {
                unsigned b[4];
                ldm_x4(b, smem_u32(Ks + kOff + nt2 * (16 * 72) + ks * 16));
                mma16(sAcc[2 * nt2],     qf[ks][0], qf[ks][1], qf[ks][2], qf[ks][3], b[0], b[1]);
                mma16(sAcc[2 * nt2 + 1], qf[ks][0], qf[ks][1], qf[ks][2], qf[ks][3], b[2], b[3]);
            }
        }

        // exp(scale + mask) -> P directly in registers (half2 packs).
        unsigned ph0[8], ph1[8];
#pragma unroll
        for (int nt = 0; nt < 8; nt++) {
            int col = nt * 8 + 2 * lc;
            float2 m0v = make_float2(0.f, 0.f);
            float2 m1v = make_float2(0.f, 0.f);
            if (mnz) {
                m0v = *(const float2*)(mask + (size_t)(qb + r0) * S + kb + col);
                m1v = *(const float2*)(mask + (size_t)(qb + r0 + 8) * S + kb + col);
            }
            float e00 = __expf(fmaf(sAcc[nt][0], 0.125f, m0v.x));
            float e01 = __expf(fmaf(sAcc[nt][1], 0.125f, m0v.y));
            float e10 = __expf(fmaf(sAcc[nt][2], 0.125f, m1v.x));
            float e11 = __expf(fmaf(sAcc[nt][3], 0.125f, m1v.y));
            rs0 += e00 + e01;
            rs1 += e10 + e11;
            __half2 h0 = __floats2half2_rn(e00, e01);
            __half2 h1 = __floats2half2_rn(e10, e11);
            ph0[nt] = *reinterpret_cast<unsigned*>(&h0);
            ph1[nt] = *reinterpret_cast<unsigned*>(&h1);
        }

        // O += P V  (P A-frags straight from registers; V via ldmatrix.trans)
#pragma unroll
        for (int ktc = 0; ktc < 4; ktc++) {
            unsigned a0 = ph0[2 * ktc];
            unsigned a1 = ph1[2 * ktc];
            unsigned a2 = ph0[2 * ktc + 1];
            unsigned a3 = ph1[2 * ktc + 1];
#pragma unroll
            for (int dtp = 0; dtp < 4; dtp++) {
                const int grp = lane >> 3;
                const int ii  = lane & 7;
                const int vrow = ktc * 16 + ((grp & 1) << 3) + ii;
                const int vcol = (dtp * 2 + (grp >> 1)) * 8;
                uint32_t addr = smem_u32(&Vs[vrow * 72 + vcol]);
                unsigned v0, v1, v2, v3;
                asm volatile(
                    "ldmatrix.sync.aligned.m8n8.x4.trans.shared.b16 {%0,%1,%2,%3}, [%4];"
                    : "=r"(v0), "=r"(v1), "=r"(v2), "=r"(v3) : "r"(addr));
                mma16(accO[dtp * 2],     a0, a1, a2, a3, v0, v1);
                mma16(accO[dtp * 2 + 1], a0, a1, a2, a3, v2, v3);
            }
        }
        __syncthreads();    // stage-s reads done before next prefetch overwrites
    }

    // full row sums (cols of a row live in the 4 lanes of a quad)
    rs0 += __shfl_xor_sync(0xffffffffu, rs0, 1);
    rs0 += __shfl_xor_sync(0xffffffffu, rs0, 2);
    rs1 += __shfl_xor_sync(0xffffffffu, rs1, 1);
    rs1 += __shfl_xor_sync(0xffffffffu, rs1, 2);
    float inv0 = 1.f / (rs0 + 1e-10f);
    float inv1 = 1.f / (rs1 + 1e-10f);

    const int bb = bh >> 4;        // bh / H
    const int hh = bh & (H - 1);
    const int mrow0 = qb + r0;
#pragma unroll
    for (int dt = 0; dt < 8; dt++) {
        int col = hh * DH + dt * 8 + 2 * lc;
        __half* dst0 = g_att + ((size_t)(bb * S + mrow0)) * D + col;
        __half* dst1 = g_att + ((size_t)(bb * S + mrow0 + 8)) * D + col;
        *(__half2*)dst0 = __floats2half2_rn(accO[dt][0] * inv0, accO[dt][1] * inv0);
        *(__half2*)dst1 = __floats2half2_rn(accO[dt][2] * inv1, accO[dt][3] * inv1);
    }
}

// ---------------------------------------------------------------------------
extern "C" void kernel_launch(void* const* d_in, const int* in_sizes, int n_in,
                              void* d_out, int out_size)
{
    (void)in_sizes; (void)n_in; (void)out_size;
    const float* x    = (const float*)d_in[0];
    const float* y    = (const float*)d_in[1];
    const float* mask = (const float*)d_in[2];
    const float* Wq   = (const float*)d_in[3];
    const float* Wk   = (const float*)d_in[4];
    const float* Wv   = (const float*)d_in[5];
    const float* Wo   = (const float*)d_in[6];
    float* out = (float*)d_out;

    static bool attr_set = false;
    if (!attr_set) {
        cudaFuncSetAttribute(flash_attn, cudaFuncAttributeMaxDynamicSharedMemorySize,
                             ATTN_SMEM);
        cudaFuncSetAttribute(qkv_gemm, cudaFuncAttributeMaxDynamicSharedMemorySize,
                             GEMM_SMEM);
        cudaFuncSetAttribute(o_gemm, cudaFuncAttributeMaxDynamicSharedMemorySize,
                             GEMM_SMEM);
        attr_set = true;
    }

    // clear mask flag (memset node; graph-capturable), then cvt + mask check
    int* flag_ptr;
    cudaGetSymbolAddress((void**)&flag_ptr, g_mask_nz);
    cudaMemsetAsync(flag_ptr, 0, sizeof(int));

    cvt_all<<<dim3(512, 1, 7), 256>>>((const float4*)x,  (const float4*)y,
                                      (const float4*)Wq, (const float4*)Wk,
                                      (const float4*)Wv, (const float4*)Wo,
                                      (const float4*)mask);

    qkv_gemm<<<dim3(D / 256, M / 128, 3), 256, GEMM_SMEM>>>();
    flash_attn<<<dim3(S / 128, B * H), 256, ATTN_SMEM>>>(mask);
    o_gemm<<<dim3(D / 256, M / 128), 256, GEMM_SMEM>>>(out);
}

// round 13
// speedup vs baseline: 1.5292x; 1.5292x over previous
#include <cuda_runtime.h>
#include <cuda_fp16.h>
#include <cstdint>

// Problem constants
constexpr int D  = 1024;   // d_model
constexpr int S  = 2048;   // sequence length
constexpr int B  = 2;      // batch
constexpr int H  = 16;     // heads
constexpr int DH = 64;     // head dim
constexpr int M  = B * S;  // 4096 rows

// Scratch (device globals; no allocations allowed). 16B-aligned for cp.async.
__device__ __align__(256) __half g_x[M * D];
__device__ __align__(256) __half g_y[M * D];
__device__ __align__(256) __half g_wq[D * D];
__device__ __align__(256) __half g_wk[D * D];
__device__ __align__(256) __half g_wv[D * D];
__device__ __align__(256) __half g_wo[D * D];
__device__ __align__(256) __half g_q[M * D];     // head-split [B,H,S,DH]
__device__ __align__(256) __half g_k[M * D];
__device__ __align__(256) __half g_v[M * D];
__device__ __align__(256) __half g_att[M * D];   // [B,S,H*DH]
__device__ int g_mask_nz;                         // 1 if mask has any nonzero

// ---------------------------------------------------------------------------
// helpers
// ---------------------------------------------------------------------------
__device__ __forceinline__ void cp16(const void* smem_dst, const void* gmem_src) {
    unsigned d = (unsigned)__cvta_generic_to_shared(smem_dst);
    asm volatile("cp.async.cg.shared.global [%0], [%1], 16;" :: "r"(d), "l"(gmem_src));
}
__device__ __forceinline__ void cp_commit() { asm volatile("cp.async.commit_group;"); }
__device__ __forceinline__ void cp_wait0()  { asm volatile("cp.async.wait_group 0;"); }
__device__ __forceinline__ void cp_wait1()  { asm volatile("cp.async.wait_group 1;"); }

__device__ __forceinline__ uint32_t smem_u32(const void* p) {
    return (uint32_t)__cvta_generic_to_shared(p);
}

// D = A*B + D   (m16n8k16, f16 inputs, f32 accum)
__device__ __forceinline__ void mma16(float c[4],
                                      unsigned a0, unsigned a1, unsigned a2, unsigned a3,
                                      unsigned b0, unsigned b1) {
    asm volatile(
        "mma.sync.aligned.m16n8k16.row.col.f32.f16.f16.f32 "
        "{%0,%1,%2,%3},{%4,%5,%6,%7},{%8,%9},{%0,%1,%2,%3};"
        : "+f"(c[0]), "+f"(c[1]), "+f"(c[2]), "+f"(c[3])
        : "r"(a0), "r"(a1), "r"(a2), "r"(a3), "r"(b0), "r"(b1));
}

__device__ __forceinline__ void ldm_x4(unsigned r[4], uint32_t addr) {
    asm volatile("ldmatrix.sync.aligned.m8n8.x4.shared.b16 {%0,%1,%2,%3}, [%4];"
                 : "=r"(r[0]), "=r"(r[1]), "=r"(r[2]), "=r"(r[3]) : "r"(addr));
}

__device__ __forceinline__ void ldm_x4_trans(unsigned r[4], uint32_t addr) {
    asm volatile("ldmatrix.sync.aligned.m8n8.x4.trans.shared.b16 {%0,%1,%2,%3}, [%4];"
                 : "=r"(r[0]), "=r"(r[1]), "=r"(r[2]), "=r"(r[3]) : "r"(addr));
}

// ---------------------------------------------------------------------------
// Merged elementwise fp16 conversion + mask nonzero check (z = 6).
// ---------------------------------------------------------------------------
__global__ void cvt_all(const float4* __restrict__ x,  const float4* __restrict__ y,
                        const float4* __restrict__ wq, const float4* __restrict__ wk,
                        const float4* __restrict__ wv, const float4* __restrict__ wo,
                        const float4* __restrict__ mask)
{
    if (blockIdx.z == 6) {     // mask check (flag pre-cleared by memset)
        int found = 0;
        const int n4 = S * S / 4;
        for (int i = blockIdx.x * blockDim.x + threadIdx.x; i < n4;
             i += gridDim.x * blockDim.x) {
            float4 v = mask[i];
            if (v.x != 0.f || v.y != 0.f || v.z != 0.f || v.w != 0.f) { found = 1; break; }
        }
        if (__syncthreads_or(found)) {
            if (threadIdx.x == 0) atomicOr(&g_mask_nz, 1);
        }
        return;
    }
    const float4* src; uint2* dst; int n4;
    switch (blockIdx.z) {
        case 0: src = x;  dst = (uint2*)g_x;  n4 = M * D / 4; break;
        case 1: src = y;  dst = (uint2*)g_y;  n4 = M * D / 4; break;
        case 2: src = wq; dst = (uint2*)g_wq; n4 = D * D / 4; break;
        case 3: src = wk; dst = (uint2*)g_wk; n4 = D * D / 4; break;
        case 4: src = wv; dst = (uint2*)g_wv; n4 = D * D / 4; break;
        default: src = wo; dst = (uint2*)g_wo; n4 = D * D / 4; break;
    }
    for (int i = blockIdx.x * blockDim.x + threadIdx.x; i < n4;
         i += gridDim.x * blockDim.x) {
        float4 v = src[i];
        __half2 h01 = __floats2half2_rn(v.x, v.y);
        __half2 h23 = __floats2half2_rn(v.z, v.w);
        uint2 u;
        u.x = *reinterpret_cast<unsigned*>(&h01);
        u.y = *reinterpret_cast<unsigned*>(&h23);
        dst[i] = u;
    }
}

// ---------------------------------------------------------------------------
// GEMM: C = A[.,1024] @ W[1024,1024]^T, fp16 mma, cp.async 2-stage pipeline.
// Block 128x128, BK=64 halfs, 256 thr, 8 warps (4m x 2n), warp tile 32x64.
// Fragments via ldmatrix.x4, batched per k-step to pipeline LDS latency.
// mode 0: f32 row-major out; mode 1: head-split f16 out.
// ---------------------------------------------------------------------------
constexpr int GSTRIDE = 72;                   // halfs per smem row (64 + 8 pad)
constexpr int GT = 128 * GSTRIDE;             // halfs per (matrix,stage)
constexpr int GEMM_SMEM = 4 * GT * 2;         // 73728 B

__device__ __forceinline__
void gemm_body(const __half* __restrict__ A, const __half* __restrict__ W,
               void* __restrict__ Cout, int mode, int bx, int by)
{
    extern __shared__ __half smh[];
    const int tid    = threadIdx.x;
    const int lane   = tid & 31;
    const int warp   = tid >> 5;
    const int warp_m = warp >> 1;    // 0..3
    const int warp_n = warp & 1;     // 0..1
    const int m0 = by * 128;
    const int n0 = bx * 128;
    const int lr = lane >> 2;        // 0..7
    const int lc = lane & 3;         // 0..3
    const int t8 = lane >> 3;        // ldmatrix tile id 0..3
    const int rI = lane & 7;         // row within tile

    // ldmatrix source offsets (in halfs)
    const int aOff = (warp_m * 32 + (t8 & 1) * 8 + rI) * GSTRIDE + (t8 >> 1) * 8;
    const int wOff = (warp_n * 64 + (t8 >> 1) * 8 + rI) * GSTRIDE + (t8 & 1) * 8;

    float acc[2][8][4];
#pragma unroll
    for (int i = 0; i < 2; i++)
#pragma unroll
        for (int j = 0; j < 8; j++)
#pragma unroll
            for (int t = 0; t < 4; t++) acc[i][j][t] = 0.f;

    auto load_stage = [&](int kc, __half* As, __half* Ws) {
        const __half* Ap = A + (size_t)m0 * D + kc * 64;
        const __half* Wp = W + (size_t)n0 * D + kc * 64;
#pragma unroll
        for (int t = 0; t < 4; t++) {
            int idx = tid + 256 * t;     // 0..1023
            int row = idx >> 3;
            int seg = idx & 7;           // 8 halfs = 16B
            cp16(As + row * GSTRIDE + seg * 8, Ap + (size_t)row * D + seg * 8);
        }
#pragma unroll
        for (int t = 0; t < 4; t++) {
            int idx = tid + 256 * t;
            int row = idx >> 3;
            int seg = idx & 7;
            cp16(Ws + row * GSTRIDE + seg * 8, Wp + (size_t)row * D + seg * 8);
        }
    };

    load_stage(0, smh, smh + 2 * GT);
    cp_commit();

    for (int kt = 0; kt < 16; kt++) {
        const int s = kt & 1;
        if (kt < 15) {
            load_stage(kt + 1, smh + (s ^ 1) * GT, smh + 2 * GT + (s ^ 1) * GT);
            cp_commit();
            cp_wait1();
        } else {
            cp_wait0();
        }
        __syncthreads();

        const __half* As = smh + s * GT;
        const __half* Ws = smh + 2 * GT + s * GT;

#pragma unroll
        for (int ks = 0; ks < 4; ks++) {
            // batch ALL fragment loads for this k-step first (issue-pipelined)
            unsigned a[2][4];
            unsigned b[4][4];
#pragma unroll
            for (int mt = 0; mt < 2; mt++)
                ldm_x4(a[mt], smem_u32(As + aOff + mt * (16 * GSTRIDE) + ks * 16));
#pragma unroll
            for (int nt2 = 0; nt2 < 4; nt2++)
                ldm_x4(b[nt2], smem_u32(Ws + wOff + nt2 * (16 * GSTRIDE) + ks * 16));
            // then all 16 HMMA
#pragma unroll
            for (int nt2 = 0; nt2 < 4; nt2++) {
#pragma unroll
                for (int mt = 0; mt < 2; mt++) {
                    mma16(acc[mt][2 * nt2],     a[mt][0], a[mt][1], a[mt][2], a[mt][3], b[nt2][0], b[nt2][1]);
                    mma16(acc[mt][2 * nt2 + 1], a[mt][0], a[mt][1], a[mt][2], a[mt][3], b[nt2][2], b[nt2][3]);
                }
            }
        }
        __syncthreads();
    }

#pragma unroll
    for (int mt = 0; mt < 2; mt++) {
#pragma unroll
        for (int nt = 0; nt < 8; nt++) {
            int rA = m0 + warp_m * 32 + mt * 16 + lr;
            int cA = n0 + warp_n * 64 + nt * 8 + 2 * lc;
#pragma unroll
            for (int half_i = 0; half_i < 2; half_i++) {
                int m = rA + half_i * 8;
                float v0 = acc[mt][nt][half_i * 2 + 0];
                float v1 = acc[mt][nt][half_i * 2 + 1];
                if (mode == 0) {
                    *(float2*)((float*)Cout + (size_t)m * D + cA) = make_float2(v0, v1);
                } else {
                    int bb = m >> 11;
                    int ss = m & (S - 1);
                    int hh = cA >> 6;
                    int dh = cA & (DH - 1);
                    __half* dst = (__half*)Cout + (((size_t)(bb * H + hh) * S + ss) * DH + dh);
                    *(__half2*)dst = __floats2half2_rn(v0, v1);
                }
            }
        }
    }
}

__global__ __launch_bounds__(256, 2)
void qkv_gemm()
{
    const __half* A; const __half* W; __half* C;
    if (blockIdx.z == 0)      { A = g_y; W = g_wq; C = g_q; }
    else if (blockIdx.z == 1) { A = g_x; W = g_wk; C = g_k; }
    else                      { A = g_x; W = g_wv; C = g_v; }
    gemm_body(A, W, C, 1, blockIdx.x, blockIdx.y);
}

__global__ __launch_bounds__(256, 2)
void o_gemm(float* __restrict__ Out)
{
    gemm_body(g_att, g_wo, Out, 0, blockIdx.x, blockIdx.y);
}

// ---------------------------------------------------------------------------
// Flash attention, naive softmax, fp16 mma, cp.async double-buffered K/V.
// CTA = 128 q-rows of one (b,h), 256 thr / 8 warps (16 rows each), k-tile 64.
// P kept in registers; K/V fragment ldmatrix batched per k-step.
// ---------------------------------------------------------------------------
constexpr int KST = 64 * 72;     // halfs per K/V stage
constexpr int ATTN_SMEM = (4 * KST + 128 * 72) * 2;   // 55296 B

__global__ __launch_bounds__(256, 2)
void flash_attn(const float* __restrict__ mask)
{
    extern __shared__ __half smh[];
    __half* Ks2 = smh;               // 2 stages of 64x72
    __half* Vs2 = smh + 2 * KST;     // 2 stages of 64x72
    __half* Qs  = smh + 4 * KST;     // 128 x 72 (Q staging only)

    const int tid  = threadIdx.x;
    const int lane = tid & 31;
    const int warp = tid >> 5;
    const int lr = lane >> 2;      // 0..7
    const int lc = lane & 3;       // 0..3
    const int t8 = lane >> 3;      // ldmatrix tile id
    const int rI = lane & 7;
    const int bh = blockIdx.y;
    const int qb = blockIdx.x * 128;
    const int mnz = g_mask_nz;     // uniform per launch

    const __half* qp    = g_q + ((size_t)bh * S + qb) * DH;
    const __half* kbase = g_k + (size_t)bh * S * DH;
    const __half* vbase = g_v + (size_t)bh * S * DH;

    const int kOff = ((t8 >> 1) * 8 + rI) * 72 + (t8 & 1) * 8;
    // V trans-ldmatrix offset per (ktc,dtp): row = ktc*16 + (t8&1)*8 + rI,
    // col = (dtp*2 + (t8>>1))*8
    const int vOffRow = ((t8 & 1) * 8 + rI) * 72;
    const int vOffCol = (t8 >> 1) * 8;

    auto kv_load = [&](int kb, __half* Kd, __half* Vd) {
#pragma unroll
        for (int t = 0; t < 2; t++) {
            int idx = tid + 256 * t;   // 0..511
            int row = idx >> 3;        // 0..63
            int seg = idx & 7;
            cp16(Kd + row * 72 + seg * 8, kbase + (size_t)(kb + row) * DH + seg * 8);
        }
#pragma unroll
        for (int t = 0; t < 2; t++) {
            int idx = tid + 256 * t;
            int row = idx >> 3;
            int seg = idx & 7;
            cp16(Vd + row * 72 + seg * 8, vbase + (size_t)(kb + row) * DH + seg * 8);
        }
    };

    // Stage Q (128 x 64 halfs)
#pragma unroll
    for (int t = 0; t < 4; t++) {
        int idx = tid + 256 * t;       // 0..1023
        int row = idx >> 3;            // 0..127
        int seg = idx & 7;
        cp16(&Qs[row * 72 + seg * 8], qp + (size_t)row * DH + seg * 8);
    }
    cp_commit();
    kv_load(0, Ks2, Vs2);
    cp_commit();
    cp_wait1();          // Q complete (KV0 may still be in flight)
    __syncthreads();

    const int r0 = warp * 16 + lr;       // warp-local q row (of 128)

    // Q fragments in registers for the whole loop (DH=64 -> 4 k16 steps)
    unsigned qf[4][4];
#pragma unroll
    for (int ks = 0; ks < 4; ks++) {
        const int kc = ks * 16 + 2 * lc;
        qf[ks][0] = *(const unsigned*)&Qs[r0 * 72 + kc];
        qf[ks][1] = *(const unsigned*)&Qs[(r0 + 8) * 72 + kc];
        qf[ks][2] = *(const unsigned*)&Qs[r0 * 72 + kc + 8];
        qf[ks][3] = *(const unsigned*)&Qs[(r0 + 8) * 72 + kc + 8];
    }

    float accO[8][4];
#pragma unroll
    for (int i = 0; i < 8; i++)
#pragma unroll
        for (int t = 0; t < 4; t++) accO[i][t] = 0.f;
    float rs0 = 0.f, rs1 = 0.f;

    for (int kt = 0; kt < S / 64; kt++) {
        const int s = kt & 1;
        if (kt < S / 64 - 1) {
            kv_load((kt + 1) * 64, Ks2 + (s ^ 1) * KST, Vs2 + (s ^ 1) * KST);
            cp_commit();
            cp_wait1();     // KV[kt] done, KV[kt+1] in flight
        } else {
            cp_wait0();
        }
        __syncthreads();    // KV[kt] visible; prior-stage reads done

        const __half* Ks = Ks2 + s * KST;
        const __half* Vs = Vs2 + s * KST;
        const int kb = kt * 64;

        // S = Q K^T  (warp: 16 x 64); batch K-frag loads per k-step
        float sAcc[8][4];
#pragma unroll
        for (int i = 0; i < 8; i++)
#pragma unroll
            for (int t = 0; t < 4; t++) sAcc[i][t] = 0.f;
#pragma unroll
        for (int ks = 0; ks < 4; ks++) {
            unsigned b[4][4];
#pragma unroll
            for (int nt2 = 0; nt2 < 4; nt2++)
                ldm_x4(b[nt2], smem_u32(Ks + kOff + nt2 * (16 * 72) + ks * 16));
#pragma unroll
            for (int nt2 = 0; nt2 < 4; nt2++) {
                mma16(sAcc[2 * nt2],     qf[ks][0], qf[ks][1], qf[ks][2], qf[ks][3], b[nt2][0], b[nt2][1]);
                mma16(sAcc[2 * nt2 + 1], qf[ks][0], qf[ks][1], qf[ks][2], qf[ks][3], b[nt2][2], b[nt2][3]);
            }
        }

        // exp(scale + mask) -> P directly in registers (half2 packs).
        unsigned ph0[8], ph1[8];
#pragma unroll
        for (int nt = 0; nt < 8; nt++) {
            int col = nt * 8 + 2 * lc;
            float2 m0v = make_float2(0.f, 0.f);
            float2 m1v = make_float2(0.f, 0.f);
            if (mnz) {
                m0v = *(const float2*)(mask + (size_t)(qb + r0) * S + kb + col);
                m1v = *(const float2*)(mask + (size_t)(qb + r0 + 8) * S + kb + col);
            }
            float e00 = __expf(fmaf(sAcc[nt][0], 0.125f, m0v.x));
            float e01 = __expf(fmaf(sAcc[nt][1], 0.125f, m0v.y));
            float e10 = __expf(fmaf(sAcc[nt][2], 0.125f, m1v.x));
            float e11 = __expf(fmaf(sAcc[nt][3], 0.125f, m1v.y));
            rs0 += e00 + e01;
            rs1 += e10 + e11;
            __half2 h0 = __floats2half2_rn(e00, e01);
            __half2 h1 = __floats2half2_rn(e10, e11);
            ph0[nt] = *reinterpret_cast<unsigned*>(&h0);
            ph1[nt] = *reinterpret_cast<unsigned*>(&h1);
        }

        // O += P V  (P A-frags from registers; batch V trans-ldmatrix per ktc)
#pragma unroll
        for (int ktc = 0; ktc < 4; ktc++) {
            unsigned a0 = ph0[2 * ktc];
            unsigned a1 = ph1[2 * ktc];
            unsigned a2 = ph0[2 * ktc + 1];
            unsigned a3 = ph1[2 * ktc + 1];
            unsigned v[4][4];
#pragma unroll
            for (int dtp = 0; dtp < 4; dtp++) {
                uint32_t addr = smem_u32(&Vs[ktc * (16 * 72) + vOffRow + dtp * 16 + vOffCol]);
                ldm_x4_trans(v[dtp], addr);
            }
#pragma unroll
            for (int dtp = 0; dtp < 4; dtp++) {
                mma16(accO[dtp * 2],     a0, a1, a2, a3, v[dtp][0], v[dtp][1]);
                mma16(accO[dtp * 2 + 1], a0, a1, a2, a3, v[dtp][2], v[dtp][3]);
            }
        }
        __syncthreads();    // stage-s reads done before next prefetch overwrites
    }

    // full row sums (cols of a row live in the 4 lanes of a quad)
    rs0 += __shfl_xor_sync(0xffffffffu, rs0, 1);
    rs0 += __shfl_xor_sync(0xffffffffu, rs0, 2);
    rs1 += __shfl_xor_sync(0xffffffffu, rs1, 1);
    rs1 += __shfl_xor_sync(0xffffffffu, rs1, 2);
    float inv0 = 1.f / (rs0 + 1e-10f);
    float inv1 = 1.f / (rs1 + 1e-10f);

    const int bb = bh >> 4;        // bh / H
    const int hh = bh & (H - 1);
    const int mrow0 = qb + r0;
#pragma unroll
    for (int dt = 0; dt < 8; dt++) {
        int col = hh * DH + dt * 8 + 2 * lc;
        __half* dst0 = g_att + ((size_t)(bb * S + mrow0)) * D + col;
        __half* dst1 = g_att + ((size_t)(bb * S + mrow0 + 8)) * D + col;
        *(__half2*)dst0 = __floats2half2_rn(accO[dt][0] * inv0, accO[dt][1] * inv0);
        *(__half2*)dst1 = __floats2half2_rn(accO[dt][2] * inv1, accO[dt][3] * inv1);
    }
}

// ---------------------------------------------------------------------------
extern "C" void kernel_launch(void* const* d_in, const int* in_sizes, int n_in,
                              void* d_out, int out_size)
{
    (void)in_sizes; (void)n_in; (void)out_size;
    const float* x    = (const float*)d_in[0];
    const float* y    = (const float*)d_in[1];
    const float* mask = (const float*)d_in[2];
    const float* Wq   = (const float*)d_in[3];
    const float* Wk   = (const float*)d_in[4];
    const float* Wv   = (const float*)d_in[5];
    const float* Wo   = (const float*)d_in[6];
    float* out = (float*)d_out;

    static bool attr_set = false;
    if (!attr_set) {
        cudaFuncSetAttribute(flash_attn, cudaFuncAttributeMaxDynamicSharedMemorySize,
                             ATTN_SMEM);
        cudaFuncSetAttribute(qkv_gemm, cudaFuncAttributeMaxDynamicSharedMemorySize,
                             GEMM_SMEM);
        cudaFuncSetAttribute(o_gemm, cudaFuncAttributeMaxDynamicSharedMemorySize,
                             GEMM_SMEM);
        attr_set = true;
    }

    // clear mask flag (memset node; graph-capturable), then cvt + mask check
    int* flag_ptr;
    cudaGetSymbolAddress((void**)&flag_ptr, g_mask_nz);
    cudaMemsetAsync(flag_ptr, 0, sizeof(int));

    cvt_all<<<dim3(512, 1, 7), 256>>>((const float4*)x,  (const float4*)y,
                                      (const float4*)Wq, (const float4*)Wk,
                                      (const float4*)Wv, (const float4*)Wo,
                                      (const float4*)mask);

    qkv_gemm<<<dim3(D / 128, M / 128, 3), 256, GEMM_SMEM>>>();
    flash_attn<<<dim3(S / 128, B * H), 256, ATTN_SMEM>>>(mask);
    o_gemm<<<dim3(D / 128, M / 128), 256, GEMM_SMEM>>>(out);
}

// round 14
// speedup vs baseline: 1.5337x; 1.0030x over previous
#include <cuda_runtime.h>
#include <cuda_fp16.h>
#include <cstdint>

// Problem constants
constexpr int D  = 1024;   // d_model
constexpr int S  = 2048;   // sequence length
constexpr int B  = 2;      // batch
constexpr int H  = 16;     // heads
constexpr int DH = 64;     // head dim
constexpr int M  = B * S;  // 4096 rows

// Scratch (device globals; no allocations allowed). 16B-aligned for cp.async.
__device__ __align__(256) __half g_x[M * D];
__device__ __align__(256) __half g_y[M * D];
__device__ __align__(256) __half g_wq[D * D];
__device__ __align__(256) __half g_wk[D * D];
__device__ __align__(256) __half g_wv[D * D];
__device__ __align__(256) __half g_wo[D * D];
__device__ __align__(256) __half g_q[M * D];     // head-split [B,H,S,DH]
__device__ __align__(256) __half g_k[M * D];
__device__ __align__(256) __half g_v[M * D];
__device__ __align__(256) __half g_att[M * D];   // [B,S,H*DH]

// Control block (cleared by one memset each call):
// [0]           work-queue counter
// [1]           mask nonzero flag
// [2..258)      q_done[m(32)][nt(8)]      (flag, 1 when q tile written)
// [258..274)    kv_cnt[b(2)][nt(8)]       (target 32 = 16 k-tiles + 16 v-tiles)
// [274..306)    att_cnt[m(32)]            (target 16 = all heads of that m-tile)
constexpr int FLQ   = 0;
constexpr int FLMNZ = 1;
constexpr int FLQD  = 2;
constexpr int FLKV  = 258;
constexpr int FLATT = 274;
constexpr int NFLAGS = 306;
__device__ int g_flags[NFLAGS];

constexpr int N_QKV   = 768;            // 8 nt * 3 proj * 32 m
constexpr int N_FLASH = 512;            // 16 h * 2 b * 16 qb
constexpr int N_O     = 256;            // 32 m * 8 n
constexpr int N_ITEMS = N_QKV + N_FLASH + N_O;   // 1536

// ---------------------------------------------------------------------------
// helpers
// ---------------------------------------------------------------------------
__device__ __forceinline__ void cp16(const void* smem_dst, const void* gmem_src) {
    unsigned d = (unsigned)__cvta_generic_to_shared(smem_dst);
    asm volatile("cp.async.cg.shared.global [%0], [%1], 16;" :: "r"(d), "l"(gmem_src));
}
__device__ __forceinline__ void cp_commit() { asm volatile("cp.async.commit_group;"); }
__device__ __forceinline__ void cp_wait0()  { asm volatile("cp.async.wait_group 0;"); }
__device__ __forceinline__ void cp_wait1()  { asm volatile("cp.async.wait_group 1;"); }

__device__ __forceinline__ uint32_t smem_u32(const void* p) {
    return (uint32_t)__cvta_generic_to_shared(p);
}

// D = A*B + D   (m16n8k16, f16 inputs, f32 accum)
__device__ __forceinline__ void mma16(float c[4],
                                      unsigned a0, unsigned a1, unsigned a2, unsigned a3,
                                      unsigned b0, unsigned b1) {
    asm volatile(
        "mma.sync.aligned.m16n8k16.row.col.f32.f16.f16.f32 "
        "{%0,%1,%2,%3},{%4,%5,%6,%7},{%8,%9},{%0,%1,%2,%3};"
        : "+f"(c[0]), "+f"(c[1]), "+f"(c[2]), "+f"(c[3])
        : "r"(a0), "r"(a1), "r"(a2), "r"(a3), "r"(b0), "r"(b1));
}

__device__ __forceinline__ void ldm_x4(unsigned r[4], uint32_t addr) {
    asm volatile("ldmatrix.sync.aligned.m8n8.x4.shared.b16 {%0,%1,%2,%3}, [%4];"
                 : "=r"(r[0]), "=r"(r[1]), "=r"(r[2]), "=r"(r[3]) : "r"(addr));
}
__device__ __forceinline__ void ldm_x4_trans(unsigned r[4], uint32_t addr) {
    asm volatile("ldmatrix.sync.aligned.m8n8.x4.trans.shared.b16 {%0,%1,%2,%3}, [%4];"
                 : "=r"(r[0]), "=r"(r[1]), "=r"(r[2]), "=r"(r[3]) : "r"(addr));
}

// ---------------------------------------------------------------------------
// Merged elementwise fp16 conversion + mask nonzero check (z = 6).
// ---------------------------------------------------------------------------
__global__ void cvt_all(const float4* __restrict__ x,  const float4* __restrict__ y,
                        const float4* __restrict__ wq, const float4* __restrict__ wk,
                        const float4* __restrict__ wv, const float4* __restrict__ wo,
                        const float4* __restrict__ mask)
{
    if (blockIdx.z == 6) {     // mask check (flag pre-cleared by memset)
        int found = 0;
        const int n4 = S * S / 4;
        for (int i = blockIdx.x * blockDim.x + threadIdx.x; i < n4;
             i += gridDim.x * blockDim.x) {
            float4 v = mask[i];
            if (v.x != 0.f || v.y != 0.f || v.z != 0.f || v.w != 0.f) { found = 1; break; }
        }
        if (__syncthreads_or(found)) {
            if (threadIdx.x == 0) atomicOr(&g_flags[FLMNZ], 1);
        }
        return;
    }
    const float4* src; uint2* dst; int n4;
    switch (blockIdx.z) {
        case 0: src = x;  dst = (uint2*)g_x;  n4 = M * D / 4; break;
        case 1: src = y;  dst = (uint2*)g_y;  n4 = M * D / 4; break;
        case 2: src = wq; dst = (uint2*)g_wq; n4 = D * D / 4; break;
        case 3: src = wk; dst = (uint2*)g_wk; n4 = D * D / 4; break;
        case 4: src = wv; dst = (uint2*)g_wv; n4 = D * D / 4; break;
        default: src = wo; dst = (uint2*)g_wo; n4 = D * D / 4; break;
    }
    for (int i = blockIdx.x * blockDim.x + threadIdx.x; i < n4;
         i += gridDim.x * blockDim.x) {
        float4 v = src[i];
        __half2 h01 = __floats2half2_rn(v.x, v.y);
        __half2 h23 = __floats2half2_rn(v.z, v.w);
        uint2 u;
        u.x = *reinterpret_cast<unsigned*>(&h01);
        u.y = *reinterpret_cast<unsigned*>(&h23);
        dst[i] = u;
    }
}

// ---------------------------------------------------------------------------
// GEMM tile: C[128x128] = A-panel @ W-panel^T, fp16 mma, cp.async 2-stage.
// 256 thr, 8 warps (4m x 2n), warp tile 32x64. Identical math to round 13.
// ---------------------------------------------------------------------------
constexpr int GSTRIDE = 72;                   // halfs per smem row (64 + 8 pad)
constexpr int GT = 128 * GSTRIDE;             // halfs per (matrix,stage)
constexpr int FUSED_SMEM = 4 * GT * 2;        // 73728 B (also covers flash's 55296)

__device__ __forceinline__
void gemm_tile(const __half* __restrict__ A, const __half* __restrict__ W,
               void* __restrict__ Cout, int mode, int bx, int by, __half* smh)
{
    const int tid    = threadIdx.x;
    const int lane   = tid & 31;
    const int warp   = tid >> 5;
    const int warp_m = warp >> 1;    // 0..3
    const int warp_n = warp & 1;     // 0..1
    const int m0 = by * 128;
    const int n0 = bx * 128;
    const int lr = lane >> 2;        // 0..7
    const int lc = lane & 3;         // 0..3
    const int t8 = lane >> 3;        // ldmatrix tile id 0..3
    const int rI = lane & 7;         // row within tile

    const int aOff = (warp_m * 32 + (t8 & 1) * 8 + rI) * GSTRIDE + (t8 >> 1) * 8;
    const int wOff = (warp_n * 64 + (t8 >> 1) * 8 + rI) * GSTRIDE + (t8 & 1) * 8;

    float acc[2][8][4];
#pragma unroll
    for (int i = 0; i < 2; i++)
#pragma unroll
        for (int j = 0; j < 8; j++)
#pragma unroll
            for (int t = 0; t < 4; t++) acc[i][j][t] = 0.f;

    auto load_stage = [&](int kc, __half* As, __half* Ws) {
        const __half* Ap = A + (size_t)m0 * D + kc * 64;
        const __half* Wp = W + (size_t)n0 * D + kc * 64;
#pragma unroll
        for (int t = 0; t < 4; t++) {
            int idx = tid + 256 * t;     // 0..1023
            int row = idx >> 3;
            int seg = idx & 7;           // 8 halfs = 16B
            cp16(As + row * GSTRIDE + seg * 8, Ap + (size_t)row * D + seg * 8);
        }
#pragma unroll
        for (int t = 0; t < 4; t++) {
            int idx = tid + 256 * t;
            int row = idx >> 3;
            int seg = idx & 7;
            cp16(Ws + row * GSTRIDE + seg * 8, Wp + (size_t)row * D + seg * 8);
        }
    };

    load_stage(0, smh, smh + 2 * GT);
    cp_commit();

    for (int kt = 0; kt < 16; kt++) {
        const int s = kt & 1;
        if (kt < 15) {
            load_stage(kt + 1, smh + (s ^ 1) * GT, smh + 2 * GT + (s ^ 1) * GT);
            cp_commit();
            cp_wait1();
        } else {
            cp_wait0();
        }
        __syncthreads();

        const __half* As = smh + s * GT;
        const __half* Ws = smh + 2 * GT + s * GT;

#pragma unroll
        for (int ks = 0; ks < 4; ks++) {
            unsigned a[2][4];
            unsigned b[4][4];
#pragma unroll
            for (int mt = 0; mt < 2; mt++)
                ldm_x4(a[mt], smem_u32(As + aOff + mt * (16 * GSTRIDE) + ks * 16));
#pragma unroll
            for (int nt2 = 0; nt2 < 4; nt2++)
                ldm_x4(b[nt2], smem_u32(Ws + wOff + nt2 * (16 * GSTRIDE) + ks * 16));
#pragma unroll
            for (int nt2 = 0; nt2 < 4; nt2++) {
#pragma unroll
                for (int mt = 0; mt < 2; mt++) {
                    mma16(acc[mt][2 * nt2],     a[mt][0], a[mt][1], a[mt][2], a[mt][3], b[nt2][0], b[nt2][1]);
                    mma16(acc[mt][2 * nt2 + 1], a[mt][0], a[mt][1], a[mt][2], a[mt][3], b[nt2][2], b[nt2][3]);
                }
            }
        }
        __syncthreads();
    }

#pragma unroll
    for (int mt = 0; mt < 2; mt++) {
#pragma unroll
        for (int nt = 0; nt < 8; nt++) {
            int rA = m0 + warp_m * 32 + mt * 16 + lr;
            int cA = n0 + warp_n * 64 + nt * 8 + 2 * lc;
#pragma unroll
            for (int half_i = 0; half_i < 2; half_i++) {
                int m = rA + half_i * 8;
                float v0 = acc[mt][nt][half_i * 2 + 0];
                float v1 = acc[mt][nt][half_i * 2 + 1];
                if (mode == 0) {
                    *(float2*)((float*)Cout + (size_t)m * D + cA) = make_float2(v0, v1);
                } else {
                    int bb = m >> 11;
                    int ss = m & (S - 1);
                    int hh = cA >> 6;
                    int dh = cA & (DH - 1);
                    __half* dst = (__half*)Cout + (((size_t)(bb * H + hh) * S + ss) * DH + dh);
                    *(__half2*)dst = __floats2half2_rn(v0, v1);
                }
            }
        }
    }
}

// ---------------------------------------------------------------------------
// Flash unit: 128 q-rows of one (b,h). Identical math to round 13.
// smem layout (within the fused 72KB buffer): K 2x64x72 | V 2x64x72 | Q 128x72
// ---------------------------------------------------------------------------
constexpr int KST = 64 * 72;     // halfs per K/V stage

__device__ __forceinline__
void flash_unit(const float* __restrict__ mask, int bb, int hh, int qx, __half* smh)
{
    __half* Ks2 = smh;
    __half* Vs2 = smh + 2 * KST;
    __half* Qs  = smh + 4 * KST;

    const int tid  = threadIdx.x;
    const int lane = tid & 31;
    const int warp = tid >> 5;
    const int lr = lane >> 2;
    const int lc = lane & 3;
    const int t8 = lane >> 3;
    const int rI = lane & 7;
    const int bh = bb * H + hh;
    const int qb = qx * 128;
    const int mnz = ((volatile int*)g_flags)[FLMNZ];

    const __half* qp    = g_q + ((size_t)bh * S + qb) * DH;
    const __half* kbase = g_k + (size_t)bh * S * DH;
    const __half* vbase = g_v + (size_t)bh * S * DH;

    const int kOff = ((t8 >> 1) * 8 + rI) * 72 + (t8 & 1) * 8;
    const int vOffRow = ((t8 & 1) * 8 + rI) * 72;
    const int vOffCol = (t8 >> 1) * 8;

    auto kv_load = [&](int kb, __half* Kd, __half* Vd) {
#pragma unroll
        for (int t = 0; t < 2; t++) {
            int idx = tid + 256 * t;
            int row = idx >> 3;
            int seg = idx & 7;
            cp16(Kd + row * 72 + seg * 8, kbase + (size_t)(kb + row) * DH + seg * 8);
        }
#pragma unroll
        for (int t = 0; t < 2; t++) {
            int idx = tid + 256 * t;
            int row = idx >> 3;
            int seg = idx & 7;
            cp16(Vd + row * 72 + seg * 8, vbase + (size_t)(kb + row) * DH + seg * 8);
        }
    };

    // Stage Q (128 x 64 halfs)
#pragma unroll
    for (int t = 0; t < 4; t++) {
        int idx = tid + 256 * t;
        int row = idx >> 3;
        int seg = idx & 7;
        cp16(&Qs[row * 72 + seg * 8], qp + (size_t)row * DH + seg * 8);
    }
    cp_commit();
    kv_load(0, Ks2, Vs2);
    cp_commit();
    cp_wait1();
    __syncthreads();

    const int r0 = warp * 16 + lr;

    unsigned qf[4][4];
#pragma unroll
    for (int ks = 0; ks < 4; ks++) {
        const int kc = ks * 16 + 2 * lc;
        qf[ks][0] = *(const unsigned*)&Qs[r0 * 72 + kc];
        qf[ks][1] = *(const unsigned*)&Qs[(r0 + 8) * 72 + kc];
        qf[ks][2] = *(const unsigned*)&Qs[r0 * 72 + kc + 8];
        qf[ks][3] = *(const unsigned*)&Qs[(r0 + 8) * 72 + kc + 8];
    }

    float accO[8][4];
#pragma unroll
    for (int i = 0; i < 8; i++)
#pragma unroll
        for (int t = 0; t < 4; t++) accO[i][t] = 0.f;
    float rs0 = 0.f, rs1 = 0.f;

    for (int kt = 0; kt < S / 64; kt++) {
        const int s = kt & 1;
        if (kt < S / 64 - 1) {
            kv_load((kt + 1) * 64, Ks2 + (s ^ 1) * KST, Vs2 + (s ^ 1) * KST);
            cp_commit();
            cp_wait1();
        } else {
            cp_wait0();
        }
        __syncthreads();

        const __half* Ks = Ks2 + s * KST;
        const __half* Vs = Vs2 + s * KST;
        const int kb = kt * 64;

        float sAcc[8][4];
#pragma unroll
        for (int i = 0; i < 8; i++)
#pragma unroll
            for (int t = 0; t < 4; t++) sAcc[i][t] = 0.f;
#pragma unroll
        for (int ks = 0; ks < 4; ks++) {
            unsigned b[4][4];
#pragma unroll
            for (int nt2 = 0; nt2 < 4; nt2++)
                ldm_x4(b[nt2], smem_u32(Ks + kOff + nt2 * (16 * 72) + ks * 16));
#pragma unroll
            for (int nt2 = 0; nt2 < 4; nt2++) {
                mma16(sAcc[2 * nt2],     qf[ks][0], qf[ks][1], qf[ks][2], qf[ks][3], b[nt2][0], b[nt2][1]);
                mma16(sAcc[2 * nt2 + 1], qf[ks][0], qf[ks][1], qf[ks][2], qf[ks][3], b[nt2][2], b[nt2][3]);
            }
        }

        unsigned ph0[8], ph1[8];
#pragma unroll
        for (int nt = 0; nt < 8; nt++) {
            int col = nt * 8 + 2 * lc;
            float2 m0v = make_float2(0.f, 0.f);
            float2 m1v = make_float2(0.f, 0.f);
            if (mnz) {
                m0v = *(const float2*)(mask + (size_t)(qb + r0) * S + kb + col);
                m1v = *(const float2*)(mask + (size_t)(qb + r0 + 8) * S + kb + col);
            }
            float e00 = __expf(fmaf(sAcc[nt][0], 0.125f, m0v.x));
            float e01 = __expf(fmaf(sAcc[nt][1], 0.125f, m0v.y));
            float e10 = __expf(fmaf(sAcc[nt][2], 0.125f, m1v.x));
            float e11 = __expf(fmaf(sAcc[nt][3], 0.125f, m1v.y));
            rs0 += e00 + e01;
            rs1 += e10 + e11;
            __half2 h0 = __floats2half2_rn(e00, e01);
            __half2 h1 = __floats2half2_rn(e10, e11);
            ph0[nt] = *reinterpret_cast<unsigned*>(&h0);
            ph1[nt] = *reinterpret_cast<unsigned*>(&h1);
        }

#pragma unroll
        for (int ktc = 0; ktc < 4; ktc++) {
            unsigned a0 = ph0[2 * ktc];
            unsigned a1 = ph1[2 * ktc];
            unsigned a2 = ph0[2 * ktc + 1];
            unsigned a3 = ph1[2 * ktc + 1];
            unsigned v[4][4];
#pragma unroll
            for (int dtp = 0; dtp < 4; dtp++) {
                uint32_t addr = smem_u32(&Vs[ktc * (16 * 72) + vOffRow + dtp * 16 + vOffCol]);
                ldm_x4_trans(v[dtp], addr);
            }
#pragma unroll
            for (int dtp = 0; dtp < 4; dtp++) {
                mma16(accO[dtp * 2],     a0, a1, a2, a3, v[dtp][0], v[dtp][1]);
                mma16(accO[dtp * 2 + 1], a0, a1, a2, a3, v[dtp][2], v[dtp][3]);
            }
        }
        __syncthreads();
    }

    rs0 += __shfl_xor_sync(0xffffffffu, rs0, 1);
    rs0 += __shfl_xor_sync(0xffffffffu, rs0, 2);
    rs1 += __shfl_xor_sync(0xffffffffu, rs1, 1);
    rs1 += __shfl_xor_sync(0xffffffffu, rs1, 2);
    float inv0 = 1.f / (rs0 + 1e-10f);
    float inv1 = 1.f / (rs1 + 1e-10f);

    const int mrow0 = qb + r0;
#pragma unroll
    for (int dt = 0; dt < 8; dt++) {
        int col = hh * DH + dt * 8 + 2 * lc;
        __half* dst0 = g_att + ((size_t)(bb * S + mrow0)) * D + col;
        __half* dst1 = g_att + ((size_t)(bb * S + mrow0 + 8)) * D + col;
        *(__half2*)dst0 = __floats2half2_rn(accO[dt][0] * inv0, accO[dt][1] * inv0);
        *(__half2*)dst1 = __floats2half2_rn(accO[dt][2] * inv1, accO[dt][3] * inv1);
    }
}

// ---------------------------------------------------------------------------
// Fused persistent kernel: work queue over qkv tiles -> flash units -> o tiles
// with fine-grained dependency flags. Deadlock-free: queue popped in order,
// deps always at lower queue indices, dep graph acyclic.
// ---------------------------------------------------------------------------
__global__ __launch_bounds__(256, 2)
void fused_mha(const float* __restrict__ mask, float* __restrict__ out)
{
    extern __shared__ __half smh[];
    __shared__ int s_item;
    const int tid = threadIdx.x;
    volatile int* vf = (volatile int*)g_flags;

    for (;;) {
        if (tid == 0) s_item = atomicAdd(&g_flags[FLQ], 1);
        __syncthreads();
        const int item = s_item;
        __syncthreads();                 // s_item reusable; smem quiesced
        if (item >= N_ITEMS) return;

        if (item < N_QKV) {
            // ---- projection tile: order nt-major, then proj, then m ----
            const int nt   = item / 96;
            const int rr   = item % 96;
            const int proj = rr / 32;
            const int m    = rr % 32;
            const __half *A, *W; __half* C;
            if (proj == 0)      { A = g_y; W = g_wq; C = g_q; }
            else if (proj == 1) { A = g_x; W = g_wk; C = g_k; }
            else                { A = g_x; W = g_wv; C = g_v; }
            gemm_tile(A, W, C, 1, nt, m, smh);
            __threadfence();
            __syncthreads();
            if (tid == 0) {
                if (proj == 0) atomicExch(&g_flags[FLQD + m * 8 + nt], 1);
                else           atomicAdd(&g_flags[FLKV + (m >> 4) * 8 + nt], 1);
            }
        } else if (item < N_QKV + N_FLASH) {
            // ---- flash unit: order h-major (deps = earliest qkv tiles) ----
            const int j  = item - N_QKV;
            const int hh = j / 32;
            const int rr = j % 32;
            const int bb = rr / 16;
            const int qx = rr % 16;
            if (tid == 0) {
                const int qi = FLQD + (bb * 16 + qx) * 8 + (hh >> 1);
                const int ki = FLKV + bb * 8 + (hh >> 1);
                while (vf[qi] != 1 || vf[ki] < 32) __nanosleep(128);
            }
            __syncthreads();
            __threadfence();
            flash_unit(mask, bb, hh, qx, smh);
            __threadfence();
            __syncthreads();
            if (tid == 0) atomicAdd(&g_flags[FLATT + bb * 16 + qx], 1);
        } else {
            // ---- O-projection tile ----
            const int j = item - N_QKV - N_FLASH;
            const int m = j / 8;
            const int n = j % 8;
            if (tid == 0) {
                while (vf[FLATT + m] < 16) __nanosleep(128);
            }
            __syncthreads();
            __threadfence();
            gemm_tile(g_att, g_wo, out, 0, n, m, smh);
        }
        __syncthreads();                 // item fully done before smem reuse
    }
}

// ---------------------------------------------------------------------------
extern "C" void kernel_launch(void* const* d_in, const int* in_sizes, int n_in,
                              void* d_out, int out_size)
{
    (void)in_sizes; (void)n_in; (void)out_size;
    const float* x    = (const float*)d_in[0];
    const float* y    = (const float*)d_in[1];
    const float* mask = (const float*)d_in[2];
    const float* Wq   = (const float*)d_in[3];
    const float* Wk   = (const float*)d_in[4];
    const float* Wv   = (const float*)d_in[5];
    const float* Wo   = (const float*)d_in[6];
    float* out = (float*)d_out;

    static bool attr_set = false;
    static int grid_blocks = 148;
    if (!attr_set) {
        cudaFuncSetAttribute(fused_mha, cudaFuncAttributeMaxDynamicSharedMemorySize,
                             FUSED_SMEM);
        int dev = 0, sm_count = 148, per_sm = 1;
        cudaGetDevice(&dev);
        cudaDeviceGetAttribute(&sm_count, cudaDevAttrMultiProcessorCount, dev);
        cudaOccupancyMaxActiveBlocksPerMultiprocessor(&per_sm, fused_mha, 256,
                                                      FUSED_SMEM);
        if (per_sm < 1) per_sm = 1;
        grid_blocks = sm_count * per_sm;
        attr_set = true;
    }

    // clear control block (queue, mask flag, dep counters) — one memset node
    int* flag_ptr;
    cudaGetSymbolAddress((void**)&flag_ptr, g_flags);
    cudaMemsetAsync(flag_ptr, 0, sizeof(int) * NFLAGS);

    cvt_all<<<dim3(512, 1, 7), 256>>>((const float4*)x,  (const float4*)y,
                                      (const float4*)Wq, (const float4*)Wk,
                                      (const float4*)Wv, (const float4*)Wo,
                                      (const float4*)mask);

    fused_mha<<<grid_blocks, 256, FUSED_SMEM>>>(mask, out);
}